// round 1
// baseline (speedup 1.0000x reference)
#include <cuda_runtime.h>
#include <math.h>

#define NB    256
#define NMEM  100000
#define CDIM  511
#define DDIM  512
#define KEYS  64
#define TOTW  640
#define KTOP  64
#define ROWS  (NB*KTOP)   // 16384

// ---------------- scratch (device globals; no allocations allowed) ----------
__device__ float g_tau[(size_t)NB*NMEM];     // 102.4 MB
__device__ float g_deltas[NB*KTOP];
__device__ int   g_topidx[NB*KTOP];
__device__ float g_mems[(size_t)ROWS*DDIM];
__device__ float g_qkvbuf[(size_t)ROWS*TOTW];
__device__ float g_att[(size_t)ROWS*DDIM];
__device__ float g_mem[(size_t)ROWS*DDIM];
__device__ float g_h[(size_t)ROWS*DDIM];
__device__ float g_t2[(size_t)ROWS*DDIM];

__device__ __forceinline__ unsigned f2key(float f) {
    unsigned b = __float_as_uint(f);
    return (b & 0x80000000u) ? ~b : (b | 0x80000000u);
}

// ---------------- generic fp32 SGEMM: C = A * op(B) (+bias)(+relu) ----------
// TB=true : B is [N,K] row-major (use B^T)    TB=false: B is [K,N] row-major
// EPI: 0 none, 1 +bias, 2 +bias+relu
template<bool TB, int EPI>
__global__ void __launch_bounds__(256) sgemm_kernel(
    const float* __restrict__ A, const float* __restrict__ Bm,
    const float* __restrict__ bias, float* __restrict__ Cm,
    int M, int N, int K, int lda, int ldb, int ldc)
{
    __shared__ float As[16][132];
    __shared__ float Bs[16][132];
    const int tid = threadIdx.x;
    const int tx = tid & 15, ty = tid >> 4;
    const int m0 = blockIdx.y * 128, n0 = blockIdx.x * 128;

    float acc[8][8];
#pragma unroll
    for (int i = 0; i < 8; i++)
#pragma unroll
        for (int j = 0; j < 8; j++) acc[i][j] = 0.f;

    for (int k0 = 0; k0 < K; k0 += 16) {
#pragma unroll
        for (int e = 0; e < 8; e++) {
            int idx = tid + e * 256;
            int m = idx >> 4, kk = idx & 15;
            int gm = m0 + m, gk = k0 + kk;
            As[kk][m] = (gm < M && gk < K) ? A[(size_t)gm * lda + gk] : 0.f;
        }
#pragma unroll
        for (int e = 0; e < 8; e++) {
            int idx = tid + e * 256;
            if (TB) {
                int n = idx >> 4, kk = idx & 15;
                int gn = n0 + n, gk = k0 + kk;
                Bs[kk][n] = (gn < N && gk < K) ? Bm[(size_t)gn * ldb + gk] : 0.f;
            } else {
                int kk = idx >> 7, n = idx & 127;
                int gn = n0 + n, gk = k0 + kk;
                Bs[kk][n] = (gn < N && gk < K) ? Bm[(size_t)gk * ldb + gn] : 0.f;
            }
        }
        __syncthreads();
#pragma unroll
        for (int kk = 0; kk < 16; kk++) {
            float af[8], bf[8];
#pragma unroll
            for (int i = 0; i < 8; i++) af[i] = As[kk][ty * 8 + i];
#pragma unroll
            for (int j = 0; j < 8; j++) bf[j] = Bs[kk][tx * 8 + j];
#pragma unroll
            for (int i = 0; i < 8; i++)
#pragma unroll
                for (int j = 0; j < 8; j++)
                    acc[i][j] = fmaf(af[i], bf[j], acc[i][j]);
        }
        __syncthreads();
    }

#pragma unroll
    for (int i = 0; i < 8; i++) {
        int gm = m0 + ty * 8 + i;
        if (gm >= M) continue;
#pragma unroll
        for (int j = 0; j < 8; j++) {
            int gn = n0 + tx * 8 + j;
            if (gn >= N) continue;
            float v = acc[i][j];
            if (EPI >= 1) v += bias[gn];
            if (EPI == 2) v = fmaxf(v, 0.f);
            Cm[(size_t)gm * ldc + gn] = v;
        }
    }
}

// ---------------- exact top-64 per row via 4-pass MSB radix select ----------
__global__ void __launch_bounds__(256) topk_kernel()
{
    const int r = blockIdx.x, tid = threadIdx.x;
    const float* row = g_tau + (size_t)r * NMEM;

    __shared__ unsigned hist[256];
    __shared__ unsigned sh_prefix;
    __shared__ int sh_need, cntA, cntB;
    __shared__ float sAval[KTOP];
    __shared__ int   sAidx[KTOP];
    __shared__ int   sBidx[256];

    unsigned prefix = 0; int need = KTOP;
    for (int p = 3; p >= 0; --p) {
        hist[tid] = 0; __syncthreads();
        const unsigned shift = p * 8;
        const unsigned maskHi = (p == 3) ? 0u : (0xFFFFFFFFu << (shift + 8));
        for (int i = tid; i < NMEM; i += 256) {
            unsigned key = f2key(row[i]);
            if ((key & maskHi) == prefix)
                atomicAdd(&hist[(key >> shift) & 255u], 1u);
        }
        __syncthreads();
        if (tid == 0) {
            int cum = 0, d = 255;
            for (; d >= 0; --d) {
                if (cum + (int)hist[d] >= need) break;
                cum += (int)hist[d];
            }
            if (d < 0) d = 0;
            sh_prefix = prefix | ((unsigned)d << shift);
            sh_need = need - cum;
        }
        __syncthreads();
        prefix = sh_prefix; need = sh_need;
        __syncthreads();
    }

    if (tid == 0) { cntA = 0; cntB = 0; }
    __syncthreads();
    for (int i = tid; i < NMEM; i += 256) {
        float v = row[i];
        unsigned key = f2key(v);
        if (key > prefix) {
            int p = atomicAdd(&cntA, 1);
            sAval[p] = v; sAidx[p] = i;
        } else if (key == prefix) {
            int p = atomicAdd(&cntB, 1);
            if (p < 256) sBidx[p] = i;
        }
    }
    __syncthreads();
    const int nA = cntA, nB = cntB;
    if (nB <= 256) {
        // ties at threshold: take the `need` smallest indices (jax tie-break)
        if (tid < nB) {
            int my = sBidx[tid], rank = 0;
            for (int j = 0; j < nB; j++) rank += (sBidx[j] < my);
            if (rank < need) { sAval[nA + rank] = row[my]; sAidx[nA + rank] = my; }
        }
    } else {
        if (tid == 0) {  // pathological fallback, never triggers in practice
            int filled = 0;
            for (int i = 0; i < NMEM && filled < need; i++)
                if (f2key(row[i]) == prefix) {
                    sAval[nA + filled] = row[i]; sAidx[nA + filled] = i; filled++;
                }
        }
    }
    __syncthreads();

    // final ordering: value descending, index ascending on ties
    if (tid < KTOP) {
        float v = sAval[tid]; int id = sAidx[tid];
        unsigned key = f2key(v);
        int rank = 0;
        for (int j = 0; j < KTOP; j++) {
            unsigned kj = f2key(sAval[j]);
            rank += (kj > key) || (kj == key && sAidx[j] < id);
        }
        g_deltas[r * KTOP + rank] = v;
        g_topidx[r * KTOP + rank] = id;
    }
}

// ---------------- mems = concat(delta, mem_c[idx]) ---------------------------
__global__ void build_mems_kernel(const float* __restrict__ mem_c)
{
    const int row = blockIdx.x, tid = threadIdx.x;
    const int idx = g_topidx[row];
    float* out = g_mems + (size_t)row * DDIM;
    if (tid == 0) out[0] = g_deltas[row];
    const float* src = mem_c + (size_t)idx * CDIM;
    for (int c = tid; c < CDIM; c += blockDim.x) out[1 + c] = src[c];
}

// ---------------- row LayerNorm (optional residual add), ddof=0 --------------
__global__ void __launch_bounds__(256) ln_kernel(
    const float* __restrict__ x, const float* __restrict__ res,
    const float* __restrict__ g, const float* __restrict__ bb,
    float* __restrict__ out, int W)
{
    const int row = blockIdx.x, tid = threadIdx.x;
    const float* xr = x + (size_t)row * W;
    const float* rr = res ? res + (size_t)row * W : nullptr;
    __shared__ float s1[256], s2[256];
    float a = 0.f, a2 = 0.f;
    for (int c = tid; c < W; c += 256) {
        float v = xr[c] + (rr ? rr[c] : 0.f);
        a += v; a2 += v * v;
    }
    s1[tid] = a; s2[tid] = a2; __syncthreads();
    for (int o = 128; o > 0; o >>= 1) {
        if (tid < o) { s1[tid] += s1[tid + o]; s2[tid] += s2[tid + o]; }
        __syncthreads();
    }
    const float mu = s1[0] / W;
    const float var = s2[0] / W - mu * mu;
    const float rs = rsqrtf(var + 1e-5f);
    for (int c = tid; c < W; c += 256) {
        float v = xr[c] + (rr ? rr[c] : 0.f);
        out[(size_t)row * W + c] = (v - mu) * rs * g[c] + bb[c];
    }
}

// ---------------- per-batch attention (64 tokens, ks=64, v=512) --------------
__global__ void __launch_bounds__(256) attn_kernel()
{
    extern __shared__ float sm[];
    float* sq = sm;                 // 64*65
    float* sk = sm + 64 * 65;       // 64*65
    float* ss = sm + 2 * 64 * 65;   // 64*65
    const int b = blockIdx.x, tid = threadIdx.x;
    const float* qkv = g_qkvbuf + (size_t)b * 64 * TOTW;

    for (int e = tid; e < 4096; e += 256) {
        int i = e >> 6, d = e & 63;
        sq[i * 65 + d] = qkv[i * TOTW + d] * 0.125f;      // key_size^-0.5
        sk[i * 65 + d] = qkv[i * TOTW + KEYS + d];
    }
    __syncthreads();
    for (int e = tid; e < 4096; e += 256) {
        int i = e >> 6, j = e & 63;
        float acc = 0.f;
#pragma unroll 16
        for (int d = 0; d < 64; d++) acc += sq[i * 65 + d] * sk[j * 65 + d];
        ss[i * 65 + j] = acc;
    }
    __syncthreads();
    if (tid < 64) {
        float m = -1e30f;
        for (int j = 0; j < 64; j++) m = fmaxf(m, ss[tid * 65 + j]);
        float s = 0.f;
        for (int j = 0; j < 64; j++) { float e = expf(ss[tid * 65 + j] - m); ss[tid * 65 + j] = e; s += e; }
        float inv = 1.f / s;
        for (int j = 0; j < 64; j++) ss[tid * 65 + j] *= inv;
    }
    __syncthreads();
    float* vt = sq;  // reuse q buffer for v chunks
    for (int dc = 0; dc < DDIM; dc += 64) {
        for (int e = tid; e < 4096; e += 256) {
            int j = e >> 6, d = e & 63;
            vt[j * 65 + d] = qkv[j * TOTW + 2 * KEYS + dc + d];
        }
        __syncthreads();
        for (int e = tid; e < 4096; e += 256) {
            int i = e >> 6, d = e & 63;
            float acc = 0.f;
#pragma unroll 16
            for (int j = 0; j < 64; j++) acc += ss[i * 65 + j] * vt[j * 65 + d];
            g_att[(size_t)(b * 64 + i) * DDIM + dc + d] = acc;
        }
        __syncthreads();
    }
}

// ---------------- host orchestration -----------------------------------------
extern "C" void kernel_launch(void* const* d_in, const int* in_sizes, int n_in,
                              void* d_out, int out_size)
{
    const float* c     = (const float*)d_in[0];
    const float* mem_c = (const float*)d_in[1];
    const float* Wqkv  = (const float*)d_in[2];
    const float* bqkv  = (const float*)d_in[3];
    const float* gq    = (const float*)d_in[4];
    const float* bq    = (const float*)d_in[5];
    const float* gm    = (const float*)d_in[6];
    const float* bm    = (const float*)d_in[7];
    const float* W1    = (const float*)d_in[8];
    const float* b1    = (const float*)d_in[9];
    const float* W2    = (const float*)d_in[10];
    const float* b2    = (const float*)d_in[11];
    const float* Ws1   = (const float*)d_in[12];
    const float* bs1   = (const float*)d_in[13];
    const float* Ws2   = (const float*)d_in[14];
    const float* bs2   = (const float*)d_in[15];
    float* out = (float*)d_out;

    float *p_tau, *p_mems, *p_qkv, *p_att, *p_mem, *p_h, *p_t2;
    cudaGetSymbolAddress((void**)&p_tau,  g_tau);
    cudaGetSymbolAddress((void**)&p_mems, g_mems);
    cudaGetSymbolAddress((void**)&p_qkv,  g_qkvbuf);
    cudaGetSymbolAddress((void**)&p_att,  g_att);
    cudaGetSymbolAddress((void**)&p_mem,  g_mem);
    cudaGetSymbolAddress((void**)&p_h,    g_h);
    cudaGetSymbolAddress((void**)&p_t2,   g_t2);

    cudaFuncSetAttribute(attn_kernel, cudaFuncAttributeMaxDynamicSharedMemorySize,
                         3 * 64 * 65 * 4);

    const dim3 blk(256);

    // 1) tau = c @ mem_c^T   [256 x 100000]
    sgemm_kernel<true, 0><<<dim3((NMEM + 127) / 128, (NB + 127) / 128), blk>>>(
        c, mem_c, nullptr, p_tau, NB, NMEM, CDIM, CDIM, CDIM, NMEM);

    // 2) exact top-64 per row (values + indices, jax ordering)
    topk_kernel<<<NB, blk>>>();

    // 3) mems = concat(deltas, mem_c[idx])   [16384 x 512]
    build_mems_kernel<<<ROWS, 128>>>(mem_c);

    // 4) qkv = LN(mems @ Wqkv + bqkv)   [16384 x 640]
    sgemm_kernel<false, 1><<<dim3(5, 128), blk>>>(
        p_mems, Wqkv, bqkv, p_qkv, ROWS, TOTW, DDIM, DDIM, TOTW, TOTW);
    ln_kernel<<<ROWS, blk>>>(p_qkv, nullptr, gq, bq, p_qkv, TOTW);

    // 5) attention per batch -> g_att  [16384 x 512]
    attn_kernel<<<NB, blk, 3 * 64 * 65 * 4>>>();

    // 6) mem = LN(mems + attended)
    ln_kernel<<<ROWS, blk>>>(p_mems, p_att, gm, bm, p_mem, DDIM);

    // 7) two residual MLP blocks: mem = LN(mlp(mem) + mem)
    for (int rep = 0; rep < 2; rep++) {
        sgemm_kernel<false, 2><<<dim3(4, 128), blk>>>(
            p_mem, W1, b1, p_h, ROWS, DDIM, DDIM, DDIM, DDIM, DDIM);
        sgemm_kernel<false, 1><<<dim3(4, 128), blk>>>(
            p_h, W2, b2, p_t2, ROWS, DDIM, DDIM, DDIM, DDIM, DDIM);
        ln_kernel<<<ROWS, blk>>>(p_t2, p_mem, gm, bm, p_mem, DDIM);
    }

    // 8) c_prime = relu(mem @ Ws1 + bs1) @ Ws2 + bs2   [16384 x 511]
    sgemm_kernel<false, 2><<<dim3(4, 128), blk>>>(
        p_mem, Ws1, bs1, p_h, ROWS, DDIM, DDIM, DDIM, DDIM, DDIM);
    sgemm_kernel<false, 1><<<dim3(4, 128), blk>>>(
        p_h, Ws2, bs2, out, ROWS, CDIM, DDIM, DDIM, CDIM, CDIM);
}

// round 3
// speedup vs baseline: 1.2036x; 1.2036x over previous
#include <cuda_runtime.h>
#include <cuda_bf16.h>
#include <mma.h>
#include <math.h>

using namespace nvcuda;
typedef __nv_bfloat16 bf16;

#define NB    256
#define NMEM  100000
#define CDIM  511
#define DDIM  512
#define KEYS  64
#define TOTW  640
#define KTOP  64
#define ROWS  (NB*KTOP)   // 16384
#define CAP   1024        // candidate cap per row

// ---------------- scratch (device globals; no allocations allowed) ----------
__device__ float g_tau[(size_t)NB*NMEM];       // approx tau, 102.4 MB
__device__ float g_deltas[NB*KTOP];
__device__ int   g_topidx[NB*KTOP];
__device__ int   g_candidx[(size_t)NB*CAP];
__device__ int   g_candcnt[NB];
__device__ float g_mems[(size_t)ROWS*DDIM];
__device__ float g_qkvbuf[(size_t)ROWS*TOTW];
__device__ float g_att[(size_t)ROWS*DDIM];
__device__ float g_mem[(size_t)ROWS*DDIM];
__device__ float g_h[(size_t)ROWS*DDIM];
__device__ float g_t2[(size_t)ROWS*DDIM];

// bf16 buffers
__device__ bf16 g_c16[(size_t)NB*DDIM];           // c padded to K=512 (hi only)
__device__ bf16 g_mc16[(size_t)NMEM*DDIM];        // mem_c padded (hi only)
__device__ bf16 g_ah[(size_t)ROWS*DDIM];          // activation split hi
__device__ bf16 g_al[(size_t)ROWS*DDIM];          // activation split lo
__device__ bf16 g_hh[(size_t)ROWS*DDIM];          // h split hi
__device__ bf16 g_hl[(size_t)ROWS*DDIM];          // h split lo
__device__ bf16 g_wqkv_h[(size_t)DDIM*TOTW], g_wqkv_l[(size_t)DDIM*TOTW];
__device__ bf16 g_w1_h[(size_t)DDIM*DDIM],  g_w1_l[(size_t)DDIM*DDIM];
__device__ bf16 g_w2_h[(size_t)DDIM*DDIM],  g_w2_l[(size_t)DDIM*DDIM];
__device__ bf16 g_ws1_h[(size_t)DDIM*DDIM], g_ws1_l[(size_t)DDIM*DDIM];
__device__ bf16 g_ws2_h[(size_t)DDIM*DDIM], g_ws2_l[(size_t)DDIM*DDIM]; // padded 511->512

__device__ __forceinline__ unsigned f2key(float f) {
    unsigned b = __float_as_uint(f);
    return (b & 0x80000000u) ? ~b : (b | 0x80000000u);
}
__device__ __forceinline__ float key2f(unsigned k) {
    unsigned b = (k & 0x80000000u) ? (k & 0x7FFFFFFFu) : ~k;
    return __uint_as_float(b);
}

// ---------------- fp32 -> bf16 hi/lo split with optional column pad ---------
__global__ void split_pad_kernel(const float* __restrict__ src,
                                 bf16* __restrict__ hi, bf16* __restrict__ lo,
                                 int rows, int scols, int dcols)
{
    size_t total = (size_t)rows * dcols;
    for (size_t idx = (size_t)blockIdx.x * blockDim.x + threadIdx.x;
         idx < total; idx += (size_t)gridDim.x * blockDim.x) {
        int r = (int)(idx / dcols), cc = (int)(idx % dcols);
        float v = (cc < scols) ? src[(size_t)r * scols + cc] : 0.f;
        bf16 h = __float2bfloat16_rn(v);
        hi[idx] = h;
        if (lo) lo[idx] = __float2bfloat16_rn(v - __bfloat162float(h));
    }
}

// ---------------- WMMA bf16 GEMM with optional 2-term split (3 MMAs) --------
// C[M,N] = A[M,K] * B   (B row-major [K,N] if !BCOL, else B is [N,K] -> B^T)
// EPI: 0 none, 1 +bias, 2 +bias+relu.  Optional split emit of C (oh/ol).
template<int SPLITS, int EPI, bool BCOL>
__global__ void __launch_bounds__(256) wgemm(
    const bf16* __restrict__ Ah, const bf16* __restrict__ Al,
    const bf16* __restrict__ Bh, const bf16* __restrict__ Bl,
    const float* __restrict__ bias, float* __restrict__ C,
    bf16* __restrict__ OH, bf16* __restrict__ OL,
    int M, int N, int K, int lda, int ldb, int ldc)
{
    constexpr int AP = 40;   // A smem leading dim (halves)
    constexpr int BP = 72;   // B smem leading dim (halves)
    __shared__ __align__(16) char sm[36864];
    bf16* sAh = (bf16*)sm;                       // 128*40*2 = 10240
    bf16* sAl = (bf16*)(sm + 10240);             // 10240
    bf16* sBh = (bf16*)(sm + 20480);             // 32*72*2 = 4608
    bf16* sBl = (bf16*)(sm + 25088);             // 4608  (total 29696)
    float* epi = (float*)sm;                     // epilogue reuse: 8*32*36*4 = 36864

    const int tid = threadIdx.x;
    const int w = tid >> 5, lane = tid & 31;
    const int wm = w >> 1, wn = w & 1;           // 4x2 warps, each 32x32
    const int m0 = blockIdx.y * 128, n0 = blockIdx.x * 64;
    const bf16 z = __float2bfloat16_rn(0.f);

    wmma::fragment<wmma::accumulator, 16, 16, 16, float> acc[2][2];
#pragma unroll
    for (int i = 0; i < 2; i++)
#pragma unroll
        for (int j = 0; j < 2; j++) wmma::fill_fragment(acc[i][j], 0.f);

    for (int k0 = 0; k0 < K; k0 += 32) {
        // load A chunk [128 x 32]
#pragma unroll
        for (int e = 0; e < 16; e++) {
            int idx = tid + e * 256;
            int m = idx >> 5, kk = idx & 31;
            int gm = m0 + m;
            bool valid = (gm < M);
            size_t off = (size_t)gm * lda + k0 + kk;
            sAh[m * AP + kk] = valid ? Ah[off] : z;
            if (SPLITS == 3) sAl[m * AP + kk] = valid ? Al[off] : z;
        }
        // load B chunk [32 x 64]
#pragma unroll
        for (int e = 0; e < 8; e++) {
            int idx = tid + e * 256;
            int kk, n;
            if (BCOL) { n = idx >> 5; kk = idx & 31; }
            else      { kk = idx >> 6; n = idx & 63; }
            int gn = n0 + n;
            bool valid = (gn < N);
            size_t off = BCOL ? ((size_t)gn * ldb + k0 + kk)
                              : ((size_t)(k0 + kk) * ldb + gn);
            sBh[kk * BP + n] = valid ? Bh[off] : z;
            if (SPLITS == 3) sBl[kk * BP + n] = valid ? Bl[off] : z;
        }
        __syncthreads();

#pragma unroll
        for (int kf = 0; kf < 32; kf += 16) {
            wmma::fragment<wmma::matrix_a, 16, 16, 16, bf16, wmma::row_major> afh[2], afl[2];
            wmma::fragment<wmma::matrix_b, 16, 16, 16, bf16, wmma::row_major> bfh[2], bfl[2];
#pragma unroll
            for (int i = 0; i < 2; i++)
                wmma::load_matrix_sync(afh[i], sAh + (wm * 32 + i * 16) * AP + kf, AP);
#pragma unroll
            for (int j = 0; j < 2; j++)
                wmma::load_matrix_sync(bfh[j], sBh + kf * BP + wn * 32 + j * 16, BP);
            if (SPLITS == 3) {
#pragma unroll
                for (int i = 0; i < 2; i++)
                    wmma::load_matrix_sync(afl[i], sAl + (wm * 32 + i * 16) * AP + kf, AP);
#pragma unroll
                for (int j = 0; j < 2; j++)
                    wmma::load_matrix_sync(bfl[j], sBl + kf * BP + wn * 32 + j * 16, BP);
            }
#pragma unroll
            for (int i = 0; i < 2; i++)
#pragma unroll
                for (int j = 0; j < 2; j++) {
                    wmma::mma_sync(acc[i][j], afh[i], bfh[j], acc[i][j]);
                    if (SPLITS == 3) {
                        wmma::mma_sync(acc[i][j], afh[i], bfl[j], acc[i][j]);
                        wmma::mma_sync(acc[i][j], afl[i], bfh[j], acc[i][j]);
                    }
                }
        }
        __syncthreads();
    }

    // epilogue: stage accumulators to smem, then guarded coalesced stores
    float* ep = epi + w * (32 * 36);
#pragma unroll
    for (int i = 0; i < 2; i++)
#pragma unroll
        for (int j = 0; j < 2; j++)
            wmma::store_matrix_sync(ep + i * 16 * 36 + j * 16, acc[i][j], 36,
                                    wmma::mem_row_major);
    __syncwarp();
#pragma unroll 4
    for (int r = 0; r < 32; r++) {
        int gm = m0 + wm * 32 + r;
        int gn = n0 + wn * 32 + lane;
        if (gm < M && gn < N) {
            float v = ep[r * 36 + lane];
            if (EPI >= 1) v += bias[gn];
            if (EPI == 2) v = fmaxf(v, 0.f);
            size_t off = (size_t)gm * ldc + gn;
            C[off] = v;
            if (OH) {
                bf16 h = __float2bfloat16_rn(v);
                OH[off] = h;
                OL[off] = __float2bfloat16_rn(v - __bfloat162float(h));
            }
        }
    }
}

// ---------------- approx top-64 radix select + margin candidate gather ------
__global__ void __launch_bounds__(256) topk_approx_kernel()
{
    const int r = blockIdx.x, tid = threadIdx.x;
    const float* row = g_tau + (size_t)r * NMEM;
    __shared__ unsigned hist[256];
    __shared__ unsigned sh_prefix;
    __shared__ int sh_need, cnt;

    unsigned prefix = 0; int need = KTOP;
    for (int p = 3; p >= 0; --p) {
        hist[tid] = 0; __syncthreads();
        const unsigned shift = p * 8;
        const unsigned maskHi = (p == 3) ? 0u : (0xFFFFFFFFu << (shift + 8));
        for (int i = tid; i < NMEM; i += 256) {
            unsigned key = f2key(row[i]);
            if ((key & maskHi) == prefix)
                atomicAdd(&hist[(key >> shift) & 255u], 1u);
        }
        __syncthreads();
        if (tid == 0) {
            int cum = 0, d = 255;
            for (; d >= 0; --d) {
                if (cum + (int)hist[d] >= need) break;
                cum += (int)hist[d];
            }
            if (d < 0) d = 0;
            sh_prefix = prefix | ((unsigned)d << shift);
            sh_need = need - cum;
        }
        __syncthreads();
        prefix = sh_prefix; need = sh_need;
        __syncthreads();
    }

    // margin: keep everything within 2.0 of the approx 64th value
    const unsigned tkey = f2key(key2f(prefix) - 2.0f);
    if (tid == 0) cnt = 0;
    __syncthreads();
    for (int i = tid; i < NMEM; i += 256) {
        if (f2key(row[i]) >= tkey) {
            int p = atomicAdd(&cnt, 1);
            if (p < CAP) g_candidx[(size_t)r * CAP + p] = i;
        }
    }
    __syncthreads();
    if (tid == 0) g_candcnt[r] = (cnt < CAP) ? cnt : CAP;
}

// ---------------- fp32 rescore (sequential-k fma: bitwise == R1 sgemm) ------
__global__ void __launch_bounds__(256) rescore_kernel(
    const float* __restrict__ c, const float* __restrict__ mem_c)
{
    const int r = blockIdx.x, tid = threadIdx.x;
    __shared__ float sc[512];
    __shared__ float scores[CAP];
    __shared__ int   cidx[CAP];
    const int nc = g_candcnt[r];

    for (int k = tid; k < CDIM; k += 256) sc[k] = c[(size_t)r * CDIM + k];
    for (int i = tid; i < nc; i += 256) cidx[i] = g_candidx[(size_t)r * CAP + i];
    __syncthreads();

    // one thread per candidate, strictly sequential fma over k (ascending)
    for (int ci = tid; ci < nc; ci += 256) {
        const float* mr = mem_c + (size_t)cidx[ci] * CDIM;
        float s = 0.f;
#pragma unroll 8
        for (int k = 0; k < CDIM; k++) s = fmaf(sc[k], mr[k], s);
        scores[ci] = s;
    }
    __syncthreads();

    // exact top-64: value descending, index ascending on ties
    for (int ci = tid; ci < nc; ci += 256) {
        float v = scores[ci]; int id = cidx[ci];
        int rank = 0;
        for (int j = 0; j < nc; j++) {
            float vj = scores[j];
            rank += (vj > v) || (vj == v && cidx[j] < id);
        }
        if (rank < KTOP) {
            g_deltas[r * KTOP + rank] = v;
            g_topidx[r * KTOP + rank] = id;
        }
    }
}

// ---------------- mems = concat(delta, mem_c[idx]) + bf16 split -------------
__global__ void build_mems_kernel(const float* __restrict__ mem_c)
{
    const int row = blockIdx.x, tid = threadIdx.x;
    const int idx = g_topidx[row];
    const float d0 = g_deltas[row];
    float* out = g_mems + (size_t)row * DDIM;
    bf16*  oh  = g_ah  + (size_t)row * DDIM;
    bf16*  ol  = g_al  + (size_t)row * DDIM;
    const float* src = mem_c + (size_t)idx * CDIM;
    for (int cpos = tid; cpos < DDIM; cpos += blockDim.x) {
        float v = (cpos == 0) ? d0 : src[cpos - 1];
        out[cpos] = v;
        bf16 h = __float2bfloat16_rn(v);
        oh[cpos] = h;
        ol[cpos] = __float2bfloat16_rn(v - __bfloat162float(h));
    }
}

// ---------------- row LayerNorm (optional residual, optional split out) -----
__global__ void __launch_bounds__(256) ln_kernel(
    const float* __restrict__ x, const float* __restrict__ res,
    const float* __restrict__ g, const float* __restrict__ bb,
    float* __restrict__ out, bf16* __restrict__ oh, bf16* __restrict__ ol, int W)
{
    const int row = blockIdx.x, tid = threadIdx.x;
    const float* xr = x + (size_t)row * W;
    const float* rr = res ? res + (size_t)row * W : nullptr;
    __shared__ float s1[256], s2[256];
    float a = 0.f, a2 = 0.f;
    for (int cpos = tid; cpos < W; cpos += 256) {
        float v = xr[cpos] + (rr ? rr[cpos] : 0.f);
        a += v; a2 += v * v;
    }
    s1[tid] = a; s2[tid] = a2; __syncthreads();
    for (int o = 128; o > 0; o >>= 1) {
        if (tid < o) { s1[tid] += s1[tid + o]; s2[tid] += s2[tid + o]; }
        __syncthreads();
    }
    const float mu = s1[0] / W;
    const float var = s2[0] / W - mu * mu;
    const float rs = rsqrtf(var + 1e-5f);
    for (int cpos = tid; cpos < W; cpos += 256) {
        float v = xr[cpos] + (rr ? rr[cpos] : 0.f);
        float y = (v - mu) * rs * g[cpos] + bb[cpos];
        size_t off = (size_t)row * W + cpos;
        out[off] = y;
        if (oh) {
            bf16 h = __float2bfloat16_rn(y);
            oh[off] = h;
            ol[off] = __float2bfloat16_rn(y - __bfloat162float(h));
        }
    }
}

// ---------------- per-batch attention (64 tokens, ks=64, v=512) --------------
__global__ void __launch_bounds__(256) attn_kernel()
{
    extern __shared__ float smf[];
    float* sq = smf;
    float* sk = smf + 64 * 65;
    float* ss = smf + 2 * 64 * 65;
    const int b = blockIdx.x, tid = threadIdx.x;
    const float* qkv = g_qkvbuf + (size_t)b * 64 * TOTW;

    for (int e = tid; e < 4096; e += 256) {
        int i = e >> 6, d = e & 63;
        sq[i * 65 + d] = qkv[i * TOTW + d] * 0.125f;
        sk[i * 65 + d] = qkv[i * TOTW + KEYS + d];
    }
    __syncthreads();
    for (int e = tid; e < 4096; e += 256) {
        int i = e >> 6, j = e & 63;
        float acc = 0.f;
#pragma unroll 16
        for (int d = 0; d < 64; d++) acc += sq[i * 65 + d] * sk[j * 65 + d];
        ss[i * 65 + j] = acc;
    }
    __syncthreads();
    if (tid < 64) {
        float m = -1e30f;
        for (int j = 0; j < 64; j++) m = fmaxf(m, ss[tid * 65 + j]);
        float s = 0.f;
        for (int j = 0; j < 64; j++) { float e = expf(ss[tid * 65 + j] - m); ss[tid * 65 + j] = e; s += e; }
        float inv = 1.f / s;
        for (int j = 0; j < 64; j++) ss[tid * 65 + j] *= inv;
    }
    __syncthreads();
    float* vt = sq;
    for (int dc = 0; dc < DDIM; dc += 64) {
        for (int e = tid; e < 4096; e += 256) {
            int j = e >> 6, d = e & 63;
            vt[j * 65 + d] = qkv[j * TOTW + 2 * KEYS + dc + d];
        }
        __syncthreads();
        for (int e = tid; e < 4096; e += 256) {
            int i = e >> 6, d = e & 63;
            float acc = 0.f;
#pragma unroll 16
            for (int j = 0; j < 64; j++) acc += ss[i * 65 + j] * vt[j * 65 + d];
            g_att[(size_t)(b * 64 + i) * DDIM + dc + d] = acc;
        }
        __syncthreads();
    }
}

// ---------------- host orchestration -----------------------------------------
extern "C" void kernel_launch(void* const* d_in, const int* in_sizes, int n_in,
                              void* d_out, int out_size)
{
    const float* c     = (const float*)d_in[0];
    const float* mem_c = (const float*)d_in[1];
    const float* Wqkv  = (const float*)d_in[2];
    const float* bqkv  = (const float*)d_in[3];
    const float* gq    = (const float*)d_in[4];
    const float* bq    = (const float*)d_in[5];
    const float* gm    = (const float*)d_in[6];
    const float* bm    = (const float*)d_in[7];
    const float* W1    = (const float*)d_in[8];
    const float* b1    = (const float*)d_in[9];
    const float* W2    = (const float*)d_in[10];
    const float* b2    = (const float*)d_in[11];
    const float* Ws1   = (const float*)d_in[12];
    const float* bs1   = (const float*)d_in[13];
    const float* Ws2   = (const float*)d_in[14];
    const float* bs2   = (const float*)d_in[15];
    float* out = (float*)d_out;

    float *p_tau, *p_mems, *p_qkv, *p_att, *p_mem, *p_h, *p_t2;
    bf16 *p_c16, *p_mc16, *p_ah, *p_al, *p_hh, *p_hl;
    bf16 *p_wqh, *p_wql, *p_w1h, *p_w1l, *p_w2h, *p_w2l, *p_s1h, *p_s1l, *p_s2h, *p_s2l;
    cudaGetSymbolAddress((void**)&p_tau,  g_tau);
    cudaGetSymbolAddress((void**)&p_mems, g_mems);
    cudaGetSymbolAddress((void**)&p_qkv,  g_qkvbuf);
    cudaGetSymbolAddress((void**)&p_att,  g_att);
    cudaGetSymbolAddress((void**)&p_mem,  g_mem);
    cudaGetSymbolAddress((void**)&p_h,    g_h);
    cudaGetSymbolAddress((void**)&p_t2,   g_t2);
    cudaGetSymbolAddress((void**)&p_c16,  g_c16);
    cudaGetSymbolAddress((void**)&p_mc16, g_mc16);
    cudaGetSymbolAddress((void**)&p_ah,   g_ah);
    cudaGetSymbolAddress((void**)&p_al,   g_al);
    cudaGetSymbolAddress((void**)&p_hh,   g_hh);
    cudaGetSymbolAddress((void**)&p_hl,   g_hl);
    cudaGetSymbolAddress((void**)&p_wqh,  g_wqkv_h);
    cudaGetSymbolAddress((void**)&p_wql,  g_wqkv_l);
    cudaGetSymbolAddress((void**)&p_w1h,  g_w1_h);
    cudaGetSymbolAddress((void**)&p_w1l,  g_w1_l);
    cudaGetSymbolAddress((void**)&p_w2h,  g_w2_h);
    cudaGetSymbolAddress((void**)&p_w2l,  g_w2_l);
    cudaGetSymbolAddress((void**)&p_s1h,  g_ws1_h);
    cudaGetSymbolAddress((void**)&p_s1l,  g_ws1_l);
    cudaGetSymbolAddress((void**)&p_s2h,  g_ws2_h);
    cudaGetSymbolAddress((void**)&p_s2l,  g_ws2_l);

    cudaFuncSetAttribute(attn_kernel, cudaFuncAttributeMaxDynamicSharedMemorySize,
                         3 * 64 * 65 * 4);
    const dim3 blk(256);

    // --- input/weight conversions ---
    split_pad_kernel<<<512, 256>>>(c,     p_c16,  nullptr, NB,   CDIM, DDIM);
    split_pad_kernel<<<2048, 256>>>(mem_c, p_mc16, nullptr, NMEM, CDIM, DDIM);
    split_pad_kernel<<<512, 256>>>(Wqkv, p_wqh, p_wql, DDIM, TOTW, TOTW);
    split_pad_kernel<<<512, 256>>>(W1,   p_w1h, p_w1l, DDIM, DDIM, DDIM);
    split_pad_kernel<<<512, 256>>>(W2,   p_w2h, p_w2l, DDIM, DDIM, DDIM);
    split_pad_kernel<<<512, 256>>>(Ws1,  p_s1h, p_s1l, DDIM, DDIM, DDIM);
    split_pad_kernel<<<512, 256>>>(Ws2,  p_s2h, p_s2l, DDIM, CDIM, DDIM);

    // --- 1) approx tau = c16 @ mc16^T (bf16 tensor cores, fp32 accum) ---
    wgemm<1, 0, true><<<dim3((NMEM + 63) / 64, 2), blk>>>(
        p_c16, nullptr, p_mc16, nullptr, nullptr, p_tau, nullptr, nullptr,
        NB, NMEM, DDIM, DDIM, DDIM, NMEM);

    // --- 2) candidate select + exact fp32 rescore (R1-identical) + top-64 ---
    topk_approx_kernel<<<NB, blk>>>();
    rescore_kernel<<<NB, blk>>>(c, mem_c);

    // --- 3) mems + split ---
    build_mems_kernel<<<ROWS, 128>>>(mem_c);

    // --- 4) qkv = LN(mems @ Wqkv + bqkv) ---
    wgemm<3, 1, false><<<dim3(10, 128), blk>>>(
        p_ah, p_al, p_wqh, p_wql, bqkv, p_qkv, nullptr, nullptr,
        ROWS, TOTW, DDIM, DDIM, TOTW, TOTW);
    ln_kernel<<<ROWS, blk>>>(p_qkv, nullptr, gq, bq, p_qkv, nullptr, nullptr, TOTW);

    // --- 5) attention ---
    attn_kernel<<<NB, blk, 3 * 64 * 65 * 4>>>();

    // --- 6) mem = LN(mems + attended)  (+ split) ---
    ln_kernel<<<ROWS, blk>>>(p_mems, p_att, gm, bm, p_mem, p_ah, p_al, DDIM);

    // --- 7) two residual MLP blocks ---
    for (int rep = 0; rep < 2; rep++) {
        wgemm<3, 2, false><<<dim3(8, 128), blk>>>(
            p_ah, p_al, p_w1h, p_w1l, b1, p_h, p_hh, p_hl,
            ROWS, DDIM, DDIM, DDIM, DDIM, DDIM);
        wgemm<3, 1, false><<<dim3(8, 128), blk>>>(
            p_hh, p_hl, p_w2h, p_w2l, b2, p_t2, nullptr, nullptr,
            ROWS, DDIM, DDIM, DDIM, DDIM, DDIM);
        ln_kernel<<<ROWS, blk>>>(p_t2, p_mem, gm, bm, p_mem, p_ah, p_al, DDIM);
    }

    // --- 8) c_prime = relu(mem @ Ws1 + bs1) @ Ws2 + bs2 ---
    wgemm<3, 2, false><<<dim3(8, 128), blk>>>(
        p_ah, p_al, p_s1h, p_s1l, bs1, p_h, p_hh, p_hl,
        ROWS, DDIM, DDIM, DDIM, DDIM, DDIM);
    wgemm<3, 1, false><<<dim3(8, 128), blk>>>(
        p_hh, p_hl, p_s2h, p_s2l, bs2, out, nullptr, nullptr,
        ROWS, CDIM, DDIM, DDIM, DDIM, CDIM);
}

// round 4
// speedup vs baseline: 2.0813x; 1.7293x over previous
#include <cuda_runtime.h>
#include <cuda_bf16.h>
#include <mma.h>
#include <math.h>

using namespace nvcuda;
typedef __nv_bfloat16 bf16;

#define NB    256
#define NMEM  100000
#define CDIM  511
#define DDIM  512
#define KEYS  64
#define TOTW  640
#define KTOP  64
#define ROWS  (NB*KTOP)   // 16384
#define CAP   1024        // candidate cap per row

// ---------------- scratch (device globals; no allocations allowed) ----------
__device__ float g_tau[(size_t)NB*NMEM];       // approx tau, 102.4 MB
__device__ float g_deltas[NB*KTOP];
__device__ int   g_topidx[NB*KTOP];
__device__ int   g_candidx[(size_t)NB*CAP];
__device__ int   g_candcnt[NB];
__device__ float g_mems[(size_t)ROWS*DDIM];
__device__ float g_qkvbuf[(size_t)ROWS*TOTW];
__device__ float g_att[(size_t)ROWS*DDIM];
__device__ float g_mem[(size_t)ROWS*DDIM];
__device__ float g_h[(size_t)ROWS*DDIM];
__device__ float g_t2[(size_t)ROWS*DDIM];

// bf16 buffers
__device__ bf16 g_c16[(size_t)NB*DDIM];
__device__ bf16 g_mc16[(size_t)NMEM*DDIM];
__device__ bf16 g_ah[(size_t)ROWS*DDIM];
__device__ bf16 g_al[(size_t)ROWS*DDIM];
__device__ bf16 g_hh[(size_t)ROWS*DDIM];
__device__ bf16 g_hl[(size_t)ROWS*DDIM];
__device__ bf16 g_wqkv_h[(size_t)DDIM*TOTW], g_wqkv_l[(size_t)DDIM*TOTW];
__device__ bf16 g_w1_h[(size_t)DDIM*DDIM],  g_w1_l[(size_t)DDIM*DDIM];
__device__ bf16 g_w2_h[(size_t)DDIM*DDIM],  g_w2_l[(size_t)DDIM*DDIM];
__device__ bf16 g_ws1_h[(size_t)DDIM*DDIM], g_ws1_l[(size_t)DDIM*DDIM];
__device__ bf16 g_ws2_h[(size_t)DDIM*DDIM], g_ws2_l[(size_t)DDIM*DDIM]; // 511->512 pad

__device__ __forceinline__ unsigned f2key(float f) {
    unsigned b = __float_as_uint(f);
    return (b & 0x80000000u) ? ~b : (b | 0x80000000u);
}
__device__ __forceinline__ float key2f(unsigned k) {
    unsigned b = (k & 0x80000000u) ? (k & 0x7FFFFFFFu) : ~k;
    return __uint_as_float(b);
}

// ---------------- fp32 -> bf16 hi/lo split with optional column pad ---------
__global__ void split_pad_kernel(const float* __restrict__ src,
                                 bf16* __restrict__ hi, bf16* __restrict__ lo,
                                 int rows, int scols, int dcols)
{
    size_t total = (size_t)rows * dcols;
    for (size_t idx = (size_t)blockIdx.x * blockDim.x + threadIdx.x;
         idx < total; idx += (size_t)gridDim.x * blockDim.x) {
        int r = (int)(idx / dcols), cc = (int)(idx % dcols);
        float v = (cc < scols) ? src[(size_t)r * scols + cc] : 0.f;
        bf16 h = __float2bfloat16_rn(v);
        hi[idx] = h;
        if (lo) lo[idx] = __float2bfloat16_rn(v - __bfloat162float(h));
    }
}

// ---------------- WMMA bf16 split GEMM: 128x128 tile, double buffered -------
// C[M,N] = A[M,K] * B.  BCOL: B is [N,K] row-major (use B^T), else [K,N].
// SPLITS: 1 -> hi only; 3 -> Ah*Bh + Ah*Bl + Al*Bh.
// EPI: 0 none, 1 +bias, 2 +bias+relu.  Optional bf16 split emit (OH/OL).
// Requirements: M % 128 == 0, K % 32 == 0, lda/ldb multiples of 8,
//               !BCOL: B rows padded so cols n0..n0+127 are readable.
template<int SPLITS, int EPI, bool BCOL>
__global__ void __launch_bounds__(256) wgemm(
    const bf16* __restrict__ Ah, const bf16* __restrict__ Al,
    const bf16* __restrict__ Bh, const bf16* __restrict__ Bl,
    const float* __restrict__ bias, float* __restrict__ C,
    bf16* __restrict__ OH, bf16* __restrict__ OL,
    int M, int N, int K, int lda, int ldb, int ldc)
{
    extern __shared__ __align__(16) char smem[];
    constexpr int AP  = 40;    // A / BCOL-B smem leading dim (halves)
    constexpr int BPR = 136;   // row-major B smem leading dim (halves)
    constexpr int STAGE = 40960;

    const int tid = threadIdx.x;
    const int w = tid >> 5, lane = tid & 31;
    const int wm = w >> 1, wn = w & 1;              // 4x2 warps, 32x64 each
    const int m0 = blockIdx.y * 128, n0 = blockIdx.x * 128;

    wmma::fragment<wmma::accumulator, 16, 16, 16, float> acc[2][4];
#pragma unroll
    for (int i = 0; i < 2; i++)
#pragma unroll
        for (int j = 0; j < 4; j++) wmma::fill_fragment(acc[i][j], 0.f);

    uint4 rAh[2], rAl[2], rBh[2], rBl[2];
    const uint4 z4 = make_uint4(0u, 0u, 0u, 0u);

    auto ldg = [&](int k0) {
#pragma unroll
        for (int e = 0; e < 2; e++) {
            int idx = tid + e * 256;
            {   // A: 128 rows x 32 cols, 4 uint4 per row
                int row = idx >> 2, c4 = idx & 3;
                size_t off = (size_t)(m0 + row) * lda + k0 + c4 * 8;
                rAh[e] = *(const uint4*)(Ah + off);
                if (SPLITS == 3) rAl[e] = *(const uint4*)(Al + off);
            }
            if (BCOL) {     // B^T tile: 128 n-rows x 32 k-cols
                int n = idx >> 2, c4 = idx & 3;
                bool v = (n0 + n) < N;
                size_t off = (size_t)(n0 + n) * ldb + k0 + c4 * 8;
                rBh[e] = v ? *(const uint4*)(Bh + off) : z4;
                if (SPLITS == 3) rBl[e] = v ? *(const uint4*)(Bl + off) : z4;
            } else {        // B tile: 32 k-rows x 128 n-cols
                int row = idx >> 4, c4 = idx & 15;
                size_t off = (size_t)(k0 + row) * ldb + n0 + c4 * 8;
                rBh[e] = *(const uint4*)(Bh + off);
                if (SPLITS == 3) rBl[e] = *(const uint4*)(Bl + off);
            }
        }
    };
    auto sts = [&](int s) {
        char* base = smem + s * STAGE;
        bf16* sAh = (bf16*)base;
        bf16* sAl = (bf16*)(base + 10240);
        bf16* sBH = (bf16*)(base + 20480);
        bf16* sBL = (bf16*)(base + 30720);
#pragma unroll
        for (int e = 0; e < 2; e++) {
            int idx = tid + e * 256;
            {   int row = idx >> 2, c4 = idx & 3;
                *(uint4*)(sAh + row * AP + c4 * 8) = rAh[e];
                if (SPLITS == 3) *(uint4*)(sAl + row * AP + c4 * 8) = rAl[e];
            }
            if (BCOL) {
                int n = idx >> 2, c4 = idx & 3;
                *(uint4*)(sBH + n * AP + c4 * 8) = rBh[e];
                if (SPLITS == 3) *(uint4*)(sBL + n * AP + c4 * 8) = rBl[e];
            } else {
                int row = idx >> 4, c4 = idx & 15;
                *(uint4*)(sBH + row * BPR + c4 * 8) = rBh[e];
                if (SPLITS == 3) *(uint4*)(sBL + row * BPR + c4 * 8) = rBl[e];
            }
        }
    };
    auto compute = [&](int s) {
        char* base = smem + s * STAGE;
        bf16* sAh = (bf16*)base;
        bf16* sAl = (bf16*)(base + 10240);
        bf16* sBH = (bf16*)(base + 20480);
        bf16* sBL = (bf16*)(base + 30720);
#pragma unroll
        for (int kf = 0; kf < 32; kf += 16) {
            wmma::fragment<wmma::matrix_a, 16, 16, 16, bf16, wmma::row_major> afh[2], afl[2];
#pragma unroll
            for (int i = 0; i < 2; i++) {
                wmma::load_matrix_sync(afh[i], sAh + (wm * 32 + i * 16) * AP + kf, AP);
                if (SPLITS == 3)
                    wmma::load_matrix_sync(afl[i], sAl + (wm * 32 + i * 16) * AP + kf, AP);
            }
            if constexpr (BCOL) {
                wmma::fragment<wmma::matrix_b, 16, 16, 16, bf16, wmma::col_major> bfh, bfl;
#pragma unroll
                for (int j = 0; j < 4; j++) {
                    wmma::load_matrix_sync(bfh, sBH + (wn * 64 + j * 16) * AP + kf, AP);
                    if (SPLITS == 3)
                        wmma::load_matrix_sync(bfl, sBL + (wn * 64 + j * 16) * AP + kf, AP);
#pragma unroll
                    for (int i = 0; i < 2; i++) {
                        wmma::mma_sync(acc[i][j], afh[i], bfh, acc[i][j]);
                        if (SPLITS == 3) {
                            wmma::mma_sync(acc[i][j], afh[i], bfl, acc[i][j]);
                            wmma::mma_sync(acc[i][j], afl[i], bfh, acc[i][j]);
                        }
                    }
                }
            } else {
                wmma::fragment<wmma::matrix_b, 16, 16, 16, bf16, wmma::row_major> bfh, bfl;
#pragma unroll
                for (int j = 0; j < 4; j++) {
                    wmma::load_matrix_sync(bfh, sBH + kf * BPR + wn * 64 + j * 16, BPR);
                    if (SPLITS == 3)
                        wmma::load_matrix_sync(bfl, sBL + kf * BPR + wn * 64 + j * 16, BPR);
#pragma unroll
                    for (int i = 0; i < 2; i++) {
                        wmma::mma_sync(acc[i][j], afh[i], bfh, acc[i][j]);
                        if (SPLITS == 3) {
                            wmma::mma_sync(acc[i][j], afh[i], bfl, acc[i][j]);
                            wmma::mma_sync(acc[i][j], afl[i], bfh, acc[i][j]);
                        }
                    }
                }
            }
        }
    };

    // double-buffered mainloop
    ldg(0); sts(0); __syncthreads();
    int cur = 0;
    for (int k0 = 0; k0 < K; k0 += 32) {
        bool more = (k0 + 32 < K);
        if (more) ldg(k0 + 32);
        compute(cur);
        if (more) {
            sts(cur ^ 1);
            __syncthreads();
            cur ^= 1;
        }
    }
    __syncthreads();

    // epilogue via smem staging (reuse pipeline smem)
    float* ep = (float*)smem + w * 2176;   // 32 x 68 per warp
#pragma unroll
    for (int i = 0; i < 2; i++)
#pragma unroll
        for (int j = 0; j < 4; j++)
            wmma::store_matrix_sync(ep + i * 16 * 68 + j * 16, acc[i][j], 68,
                                    wmma::mem_row_major);
    __syncwarp();
#pragma unroll 4
    for (int r = 0; r < 32; r++) {
        int gm = m0 + wm * 32 + r;
#pragma unroll
        for (int it = 0; it < 2; it++) {
            int gn = n0 + wn * 64 + it * 32 + lane;
            if (gn < N) {
                float v = ep[r * 68 + it * 32 + lane];
                if (EPI >= 1) v += bias[gn];
                if (EPI == 2) v = fmaxf(v, 0.f);
                size_t off = (size_t)gm * ldc + gn;
                C[off] = v;
                if (OH) {
                    bf16 h = __float2bfloat16_rn(v);
                    OH[off] = h;
                    OL[off] = __float2bfloat16_rn(v - __bfloat162float(h));
                }
            }
        }
    }
}

// ---------------- approx top-64 radix select + margin candidate gather ------
__global__ void __launch_bounds__(256) topk_approx_kernel()
{
    const int r = blockIdx.x, tid = threadIdx.x;
    const float* row = g_tau + (size_t)r * NMEM;
    __shared__ unsigned hist[256];
    __shared__ unsigned sh_prefix;
    __shared__ int sh_need, cnt;

    unsigned prefix = 0; int need = KTOP;
    for (int p = 3; p >= 0; --p) {
        hist[tid] = 0; __syncthreads();
        const unsigned shift = p * 8;
        const unsigned maskHi = (p == 3) ? 0u : (0xFFFFFFFFu << (shift + 8));
        for (int i = tid; i < NMEM; i += 256) {
            unsigned key = f2key(row[i]);
            if ((key & maskHi) == prefix)
                atomicAdd(&hist[(key >> shift) & 255u], 1u);
        }
        __syncthreads();
        if (tid == 0) {
            int cum = 0, d = 255;
            for (; d >= 0; --d) {
                if (cum + (int)hist[d] >= need) break;
                cum += (int)hist[d];
            }
            if (d < 0) d = 0;
            sh_prefix = prefix | ((unsigned)d << shift);
            sh_need = need - cum;
        }
        __syncthreads();
        prefix = sh_prefix; need = sh_need;
        __syncthreads();
    }

    const unsigned tkey = f2key(key2f(prefix) - 2.0f);
    if (tid == 0) cnt = 0;
    __syncthreads();
    for (int i = tid; i < NMEM; i += 256) {
        if (f2key(row[i]) >= tkey) {
            int p = atomicAdd(&cnt, 1);
            if (p < CAP) g_candidx[(size_t)r * CAP + p] = i;
        }
    }
    __syncthreads();
    if (tid == 0) g_candcnt[r] = (cnt < CAP) ? cnt : CAP;
}

// ---------------- fp32 rescore (sequential-k fma, R1-identical) -------------
__global__ void __launch_bounds__(256) rescore_kernel(
    const float* __restrict__ c, const float* __restrict__ mem_c)
{
    const int r = blockIdx.x, tid = threadIdx.x;
    __shared__ float sc[512];
    __shared__ float scores[CAP];
    __shared__ int   cidx[CAP];
    const int nc = g_candcnt[r];

    for (int k = tid; k < CDIM; k += 256) sc[k] = c[(size_t)r * CDIM + k];
    for (int i = tid; i < nc; i += 256) cidx[i] = g_candidx[(size_t)r * CAP + i];
    __syncthreads();

    for (int ci = tid; ci < nc; ci += 256) {
        const float* mr = mem_c + (size_t)cidx[ci] * CDIM;
        float s = 0.f;
#pragma unroll 8
        for (int k = 0; k < CDIM; k++) s = fmaf(sc[k], mr[k], s);
        scores[ci] = s;
    }
    __syncthreads();

    for (int ci = tid; ci < nc; ci += 256) {
        float v = scores[ci]; int id = cidx[ci];
        int rank = 0;
        for (int j = 0; j < nc; j++) {
            float vj = scores[j];
            rank += (vj > v) || (vj == v && cidx[j] < id);
        }
        if (rank < KTOP) {
            g_deltas[r * KTOP + rank] = v;
            g_topidx[r * KTOP + rank] = id;
        }
    }
}

// ---------------- mems = concat(delta, mem_c[idx]) + bf16 split -------------
__global__ void build_mems_kernel(const float* __restrict__ mem_c)
{
    const int row = blockIdx.x, tid = threadIdx.x;
    const int idx = g_topidx[row];
    const float d0 = g_deltas[row];
    float* out = g_mems + (size_t)row * DDIM;
    bf16*  oh  = g_ah  + (size_t)row * DDIM;
    bf16*  ol  = g_al  + (size_t)row * DDIM;
    const float* src = mem_c + (size_t)idx * CDIM;
    for (int cpos = tid; cpos < DDIM; cpos += blockDim.x) {
        float v = (cpos == 0) ? d0 : src[cpos - 1];
        out[cpos] = v;
        bf16 h = __float2bfloat16_rn(v);
        oh[cpos] = h;
        ol[cpos] = __float2bfloat16_rn(v - __bfloat162float(h));
    }
}

// ---------------- row LayerNorm (optional residual, optional split out) -----
__global__ void __launch_bounds__(256) ln_kernel(
    const float* __restrict__ x, const float* __restrict__ res,
    const float* __restrict__ g, const float* __restrict__ bb,
    float* __restrict__ out, bf16* __restrict__ oh, bf16* __restrict__ ol, int W)
{
    const int row = blockIdx.x, tid = threadIdx.x;
    const float* xr = x + (size_t)row * W;
    const float* rr = res ? res + (size_t)row * W : nullptr;
    __shared__ float s1[256], s2[256];
    float a = 0.f, a2 = 0.f;
    for (int cpos = tid; cpos < W; cpos += 256) {
        float v = xr[cpos] + (rr ? rr[cpos] : 0.f);
        a += v; a2 += v * v;
    }
    s1[tid] = a; s2[tid] = a2; __syncthreads();
    for (int o = 128; o > 0; o >>= 1) {
        if (tid < o) { s1[tid] += s1[tid + o]; s2[tid] += s2[tid + o]; }
        __syncthreads();
    }
    const float mu = s1[0] / W;
    const float var = s2[0] / W - mu * mu;
    const float rs = rsqrtf(var + 1e-5f);
    for (int cpos = tid; cpos < W; cpos += 256) {
        float v = xr[cpos] + (rr ? rr[cpos] : 0.f);
        float y = (v - mu) * rs * g[cpos] + bb[cpos];
        size_t off = (size_t)row * W + cpos;
        out[off] = y;
        if (oh) {
            bf16 h = __float2bfloat16_rn(y);
            oh[off] = h;
            ol[off] = __float2bfloat16_rn(y - __bfloat162float(h));
        }
    }
}

// ---------------- per-batch attention (64 tokens, ks=64, v=512) --------------
__global__ void __launch_bounds__(256) attn_kernel()
{
    extern __shared__ float smf[];
    float* sq = smf;
    float* sk = smf + 64 * 65;
    float* ss = smf + 2 * 64 * 65;
    const int b = blockIdx.x, tid = threadIdx.x;
    const float* qkv = g_qkvbuf + (size_t)b * 64 * TOTW;

    for (int e = tid; e < 4096; e += 256) {
        int i = e >> 6, d = e & 63;
        sq[i * 65 + d] = qkv[i * TOTW + d] * 0.125f;
        sk[i * 65 + d] = qkv[i * TOTW + KEYS + d];
    }
    __syncthreads();
    for (int e = tid; e < 4096; e += 256) {
        int i = e >> 6, j = e & 63;
        float acc = 0.f;
#pragma unroll 16
        for (int d = 0; d < 64; d++) acc += sq[i * 65 + d] * sk[j * 65 + d];
        ss[i * 65 + j] = acc;
    }
    __syncthreads();
    if (tid < 64) {
        float m = -1e30f;
        for (int j = 0; j < 64; j++) m = fmaxf(m, ss[tid * 65 + j]);
        float s = 0.f;
        for (int j = 0; j < 64; j++) { float e = expf(ss[tid * 65 + j] - m); ss[tid * 65 + j] = e; s += e; }
        float inv = 1.f / s;
        for (int j = 0; j < 64; j++) ss[tid * 65 + j] *= inv;
    }
    __syncthreads();
    float* vt = sq;
    for (int dc = 0; dc < DDIM; dc += 64) {
        for (int e = tid; e < 4096; e += 256) {
            int j = e >> 6, d = e & 63;
            vt[j * 65 + d] = qkv[j * TOTW + 2 * KEYS + dc + d];
        }
        __syncthreads();
        for (int e = tid; e < 4096; e += 256) {
            int i = e >> 6, d = e & 63;
            float acc = 0.f;
#pragma unroll 16
            for (int j = 0; j < 64; j++) acc += ss[i * 65 + j] * vt[j * 65 + d];
            g_att[(size_t)(b * 64 + i) * DDIM + dc + d] = acc;
        }
        __syncthreads();
    }
}

// ---------------- host orchestration -----------------------------------------
extern "C" void kernel_launch(void* const* d_in, const int* in_sizes, int n_in,
                              void* d_out, int out_size)
{
    const float* c     = (const float*)d_in[0];
    const float* mem_c = (const float*)d_in[1];
    const float* Wqkv  = (const float*)d_in[2];
    const float* bqkv  = (const float*)d_in[3];
    const float* gq    = (const float*)d_in[4];
    const float* bq    = (const float*)d_in[5];
    const float* gm    = (const float*)d_in[6];
    const float* bm    = (const float*)d_in[7];
    const float* W1    = (const float*)d_in[8];
    const float* b1    = (const float*)d_in[9];
    const float* W2    = (const float*)d_in[10];
    const float* b2    = (const float*)d_in[11];
    const float* Ws1   = (const float*)d_in[12];
    const float* bs1   = (const float*)d_in[13];
    const float* Ws2   = (const float*)d_in[14];
    const float* bs2   = (const float*)d_in[15];
    float* out = (float*)d_out;

    float *p_tau, *p_mems, *p_qkv, *p_att, *p_mem, *p_h, *p_t2;
    bf16 *p_c16, *p_mc16, *p_ah, *p_al, *p_hh, *p_hl;
    bf16 *p_wqh, *p_wql, *p_w1h, *p_w1l, *p_w2h, *p_w2l, *p_s1h, *p_s1l, *p_s2h, *p_s2l;
    cudaGetSymbolAddress((void**)&p_tau,  g_tau);
    cudaGetSymbolAddress((void**)&p_mems, g_mems);
    cudaGetSymbolAddress((void**)&p_qkv,  g_qkvbuf);
    cudaGetSymbolAddress((void**)&p_att,  g_att);
    cudaGetSymbolAddress((void**)&p_mem,  g_mem);
    cudaGetSymbolAddress((void**)&p_h,    g_h);
    cudaGetSymbolAddress((void**)&p_t2,   g_t2);
    cudaGetSymbolAddress((void**)&p_c16,  g_c16);
    cudaGetSymbolAddress((void**)&p_mc16, g_mc16);
    cudaGetSymbolAddress((void**)&p_ah,   g_ah);
    cudaGetSymbolAddress((void**)&p_al,   g_al);
    cudaGetSymbolAddress((void**)&p_hh,   g_hh);
    cudaGetSymbolAddress((void**)&p_hl,   g_hl);
    cudaGetSymbolAddress((void**)&p_wqh,  g_wqkv_h);
    cudaGetSymbolAddress((void**)&p_wql,  g_wqkv_l);
    cudaGetSymbolAddress((void**)&p_w1h,  g_w1_h);
    cudaGetSymbolAddress((void**)&p_w1l,  g_w1_l);
    cudaGetSymbolAddress((void**)&p_w2h,  g_w2_h);
    cudaGetSymbolAddress((void**)&p_w2l,  g_w2_l);
    cudaGetSymbolAddress((void**)&p_s1h,  g_ws1_h);
    cudaGetSymbolAddress((void**)&p_s1l,  g_ws1_l);
    cudaGetSymbolAddress((void**)&p_s2h,  g_ws2_h);
    cudaGetSymbolAddress((void**)&p_s2l,  g_ws2_l);

    const int WG_SMEM = 81920;
    cudaFuncSetAttribute(wgemm<1, 0, true>,  cudaFuncAttributeMaxDynamicSharedMemorySize, WG_SMEM);
    cudaFuncSetAttribute(wgemm<3, 1, false>, cudaFuncAttributeMaxDynamicSharedMemorySize, WG_SMEM);
    cudaFuncSetAttribute(wgemm<3, 2, false>, cudaFuncAttributeMaxDynamicSharedMemorySize, WG_SMEM);
    cudaFuncSetAttribute(attn_kernel, cudaFuncAttributeMaxDynamicSharedMemorySize,
                         3 * 64 * 65 * 4);
    const dim3 blk(256);

    // --- input/weight conversions ---
    split_pad_kernel<<<512, 256>>>(c,     p_c16,  nullptr, NB,   CDIM, DDIM);
    split_pad_kernel<<<2048, 256>>>(mem_c, p_mc16, nullptr, NMEM, CDIM, DDIM);
    split_pad_kernel<<<512, 256>>>(Wqkv, p_wqh, p_wql, DDIM, TOTW, TOTW);
    split_pad_kernel<<<512, 256>>>(W1,   p_w1h, p_w1l, DDIM, DDIM, DDIM);
    split_pad_kernel<<<512, 256>>>(W2,   p_w2h, p_w2l, DDIM, DDIM, DDIM);
    split_pad_kernel<<<512, 256>>>(Ws1,  p_s1h, p_s1l, DDIM, DDIM, DDIM);
    split_pad_kernel<<<512, 256>>>(Ws2,  p_s2h, p_s2l, DDIM, CDIM, DDIM);

    // --- 1) approx tau = c16 @ mc16^T ---
    wgemm<1, 0, true><<<dim3((NMEM + 127) / 128, 2), blk, WG_SMEM>>>(
        p_c16, nullptr, p_mc16, nullptr, nullptr, p_tau, nullptr, nullptr,
        NB, NMEM, DDIM, DDIM, DDIM, NMEM);

    // --- 2) candidate select + exact fp32 rescore + exact top-64 ---
    topk_approx_kernel<<<NB, blk>>>();
    rescore_kernel<<<NB, blk>>>(c, mem_c);

    // --- 3) mems + split ---
    build_mems_kernel<<<ROWS, 128>>>(mem_c);

    // --- 4) qkv = LN(mems @ Wqkv + bqkv) ---
    wgemm<3, 1, false><<<dim3(5, 128), blk, WG_SMEM>>>(
        p_ah, p_al, p_wqh, p_wql, bqkv, p_qkv, nullptr, nullptr,
        ROWS, TOTW, DDIM, DDIM, TOTW, TOTW);
    ln_kernel<<<ROWS, blk>>>(p_qkv, nullptr, gq, bq, p_qkv, nullptr, nullptr, TOTW);

    // --- 5) attention ---
    attn_kernel<<<NB, blk, 3 * 64 * 65 * 4>>>();

    // --- 6) mem = LN(mems + attended)  (+ split) ---
    ln_kernel<<<ROWS, blk>>>(p_mems, p_att, gm, bm, p_mem, p_ah, p_al, DDIM);

    // --- 7) two residual MLP blocks ---
    for (int rep = 0; rep < 2; rep++) {
        wgemm<3, 2, false><<<dim3(4, 128), blk, WG_SMEM>>>(
            p_ah, p_al, p_w1h, p_w1l, b1, p_h, p_hh, p_hl,
            ROWS, DDIM, DDIM, DDIM, DDIM, DDIM);
        wgemm<3, 1, false><<<dim3(4, 128), blk, WG_SMEM>>>(
            p_hh, p_hl, p_w2h, p_w2l, b2, p_t2, nullptr, nullptr,
            ROWS, DDIM, DDIM, DDIM, DDIM, DDIM);
        ln_kernel<<<ROWS, blk>>>(p_t2, p_mem, gm, bm, p_mem, p_ah, p_al, DDIM);
    }

    // --- 8) c_prime = relu(mem @ Ws1 + bs1) @ Ws2 + bs2 ---
    wgemm<3, 2, false><<<dim3(4, 128), blk, WG_SMEM>>>(
        p_ah, p_al, p_s1h, p_s1l, bs1, p_h, p_hh, p_hl,
        ROWS, DDIM, DDIM, DDIM, DDIM, DDIM);
    wgemm<3, 1, false><<<dim3(4, 128), blk, WG_SMEM>>>(
        p_hh, p_hl, p_s2h, p_s2l, bs2, out, nullptr, nullptr,
        ROWS, CDIM, DDIM, DDIM, DDIM, CDIM);
}

// round 5
// speedup vs baseline: 2.5420x; 1.2214x over previous
#include <cuda_runtime.h>
#include <cuda_bf16.h>
#include <mma.h>
#include <math.h>

using namespace nvcuda;
typedef __nv_bfloat16 bf16;

#define NB    256
#define NMEM  100000
#define CDIM  511
#define DDIM  512
#define KEYS  64
#define TOTW  640
#define KTOP  64
#define ROWS  (NB*KTOP)   // 16384
#define CAP   1024        // candidate cap per row

// ---------------- scratch (device globals; no allocations allowed) ----------
__device__ bf16  g_tau16[(size_t)NB*NMEM];     // approx tau in bf16, 51.2 MB
__device__ float g_deltas[NB*KTOP];
__device__ int   g_topidx[NB*KTOP];
__device__ int   g_candidx[(size_t)NB*CAP];
__device__ int   g_candcnt[NB];
__device__ float g_mems[(size_t)ROWS*DDIM];
__device__ float g_qkvbuf[(size_t)ROWS*TOTW];
__device__ float g_att[(size_t)ROWS*DDIM];
__device__ float g_mem[(size_t)ROWS*DDIM];
__device__ float g_h[(size_t)ROWS*DDIM];
__device__ float g_t2[(size_t)ROWS*DDIM];

// bf16 buffers
__device__ bf16 g_c16[(size_t)NB*DDIM];
__device__ bf16 g_mc16[(size_t)NMEM*DDIM];
__device__ bf16 g_ah[(size_t)ROWS*DDIM];
__device__ bf16 g_al[(size_t)ROWS*DDIM];
__device__ bf16 g_hh[(size_t)ROWS*DDIM];
__device__ bf16 g_hl[(size_t)ROWS*DDIM];
__device__ bf16 g_wqkv_h[(size_t)DDIM*TOTW], g_wqkv_l[(size_t)DDIM*TOTW];
__device__ bf16 g_w1_h[(size_t)DDIM*DDIM],  g_w1_l[(size_t)DDIM*DDIM];
__device__ bf16 g_w2_h[(size_t)DDIM*DDIM],  g_w2_l[(size_t)DDIM*DDIM];
__device__ bf16 g_ws1_h[(size_t)DDIM*DDIM], g_ws1_l[(size_t)DDIM*DDIM];
__device__ bf16 g_ws2_h[(size_t)DDIM*DDIM], g_ws2_l[(size_t)DDIM*DDIM]; // 511->512 pad

// ---------------- cp.async helpers ------------------------------------------
__device__ __forceinline__ void cp16(void* dst_smem, const void* src, bool pred) {
    unsigned d = (unsigned)__cvta_generic_to_shared(dst_smem);
    int sz = pred ? 16 : 0;
    asm volatile("cp.async.cg.shared.global [%0], [%1], 16, %2;\n"
                 :: "r"(d), "l"(src), "r"(sz));
}
__device__ __forceinline__ void cp_commit() {
    asm volatile("cp.async.commit_group;\n");
}
template<int NN>
__device__ __forceinline__ void cp_wait() {
    asm volatile("cp.async.wait_group %0;\n" :: "n"(NN));
}

__device__ __forceinline__ unsigned short f2key16(unsigned short b) {
    return (b & 0x8000u) ? (unsigned short)(~b) : (unsigned short)(b | 0x8000u);
}
__device__ __forceinline__ float key16_to_f(unsigned short k) {
    unsigned short raw = (k & 0x8000u) ? (unsigned short)(k & 0x7FFFu)
                                       : (unsigned short)(~k);
    __nv_bfloat16_raw br; br.x = raw;
    return __bfloat162float((bf16)br);
}

// ---------------- fp32 -> bf16 hi/lo split with optional column pad ---------
__global__ void split_pad_kernel(const float* __restrict__ src,
                                 bf16* __restrict__ hi, bf16* __restrict__ lo,
                                 int rows, int scols, int dcols)
{
    size_t total = (size_t)rows * dcols;
    for (size_t idx = (size_t)blockIdx.x * blockDim.x + threadIdx.x;
         idx < total; idx += (size_t)gridDim.x * blockDim.x) {
        int r = (int)(idx / dcols), cc = (int)(idx % dcols);
        float v = (cc < scols) ? src[(size_t)r * scols + cc] : 0.f;
        bf16 h = __float2bfloat16_rn(v);
        hi[idx] = h;
        if (lo) lo[idx] = __float2bfloat16_rn(v - __bfloat162float(h));
    }
}

// ---------------- WMMA bf16 split GEMM: 128x128 tile, cp.async pipeline -----
// C[M,N] = A[M,K] * B.  BCOL: B is [N,K] row-major (use B^T), else [K,N].
// SPLITS: 1 -> hi only; 3 -> Ah*Bh + Ah*Bl + Al*Bh.
// EPI: 0 none, 1 +bias, 2 +bias+relu.
// Outputs: fp32 C if non-null; bf16 OH (and OL split) if non-null.
// Requirements: M % 128 == 0, K % 32 == 0, lda/ldb multiples of 8.
template<int SPLITS, int EPI, bool BCOL>
__global__ void __launch_bounds__(256) wgemm(
    const bf16* __restrict__ Ah, const bf16* __restrict__ Al,
    const bf16* __restrict__ Bh, const bf16* __restrict__ Bl,
    const float* __restrict__ bias, float* __restrict__ C,
    bf16* __restrict__ OH, bf16* __restrict__ OL,
    int M, int N, int K, int lda, int ldb, int ldc)
{
    extern __shared__ __align__(16) char smem[];
    constexpr int AP  = 40;    // A / BCOL-B smem leading dim (halves)
    constexpr int BPR = 136;   // row-major B smem leading dim (halves)
    constexpr int STAGE = 40960;

    const int tid = threadIdx.x;
    const int w = tid >> 5, lane = tid & 31;
    const int wm = w >> 1, wn = w & 1;              // 4x2 warps, 32x64 each
    const int m0 = blockIdx.y * 128, n0 = blockIdx.x * 128;

    wmma::fragment<wmma::accumulator, 16, 16, 16, float> acc[2][4];
#pragma unroll
    for (int i = 0; i < 2; i++)
#pragma unroll
        for (int j = 0; j < 4; j++) wmma::fill_fragment(acc[i][j], 0.f);

    // async copy of one K-chunk into stage s
    auto issue = [&](int k0, int s) {
        char* base = smem + s * STAGE;
        bf16* sAh = (bf16*)base;
        bf16* sAl = (bf16*)(base + 10240);
        bf16* sBH = (bf16*)(base + 20480);
        bf16* sBL = (bf16*)(base + 30720);
#pragma unroll
        for (int e = 0; e < 2; e++) {
            int idx = tid + e * 256;
            {   // A: 128 rows x 32 halves
                int row = idx >> 2, c4 = idx & 3;
                size_t off = (size_t)(m0 + row) * lda + k0 + c4 * 8;
                cp16(sAh + row * AP + c4 * 8, Ah + off, true);
                if (SPLITS == 3) cp16(sAl + row * AP + c4 * 8, Al + off, true);
            }
            if (BCOL) {     // B^T tile: 128 n-rows x 32 k-halves
                int n = idx >> 2, c4 = idx & 3;
                bool v = (n0 + n) < N;
                size_t off = v ? ((size_t)(n0 + n) * ldb + k0 + c4 * 8) : 0;
                cp16(sBH + n * AP + c4 * 8, Bh + off, v);
                if (SPLITS == 3) cp16(sBL + n * AP + c4 * 8, Bl + off, v);
            } else {        // B tile: 32 k-rows x 128 n-halves
                int row = idx >> 4, c4 = idx & 15;
                size_t off = (size_t)(k0 + row) * ldb + n0 + c4 * 8;
                cp16(sBH + row * BPR + c4 * 8, Bh + off, true);
                if (SPLITS == 3) cp16(sBL + row * BPR + c4 * 8, Bl + off, true);
            }
        }
        cp_commit();
    };

    auto compute = [&](int s) {
        char* base = smem + s * STAGE;
        bf16* sAh = (bf16*)base;
        bf16* sAl = (bf16*)(base + 10240);
        bf16* sBH = (bf16*)(base + 20480);
        bf16* sBL = (bf16*)(base + 30720);
#pragma unroll
        for (int kf = 0; kf < 32; kf += 16) {
            wmma::fragment<wmma::matrix_a, 16, 16, 16, bf16, wmma::row_major> afh[2], afl[2];
#pragma unroll
            for (int i = 0; i < 2; i++) {
                wmma::load_matrix_sync(afh[i], sAh + (wm * 32 + i * 16) * AP + kf, AP);
                if (SPLITS == 3)
                    wmma::load_matrix_sync(afl[i], sAl + (wm * 32 + i * 16) * AP + kf, AP);
            }
            if constexpr (BCOL) {
                wmma::fragment<wmma::matrix_b, 16, 16, 16, bf16, wmma::col_major> bfh, bfl;
#pragma unroll
                for (int j = 0; j < 4; j++) {
                    wmma::load_matrix_sync(bfh, sBH + (wn * 64 + j * 16) * AP + kf, AP);
                    if (SPLITS == 3)
                        wmma::load_matrix_sync(bfl, sBL + (wn * 64 + j * 16) * AP + kf, AP);
#pragma unroll
                    for (int i = 0; i < 2; i++) {
                        wmma::mma_sync(acc[i][j], afh[i], bfh, acc[i][j]);
                        if (SPLITS == 3) {
                            wmma::mma_sync(acc[i][j], afh[i], bfl, acc[i][j]);
                            wmma::mma_sync(acc[i][j], afl[i], bfh, acc[i][j]);
                        }
                    }
                }
            } else {
                wmma::fragment<wmma::matrix_b, 16, 16, 16, bf16, wmma::row_major> bfh, bfl;
#pragma unroll
                for (int j = 0; j < 4; j++) {
                    wmma::load_matrix_sync(bfh, sBH + kf * BPR + wn * 64 + j * 16, BPR);
                    if (SPLITS == 3)
                        wmma::load_matrix_sync(bfl, sBL + kf * BPR + wn * 64 + j * 16, BPR);
#pragma unroll
                    for (int i = 0; i < 2; i++) {
                        wmma::mma_sync(acc[i][j], afh[i], bfh, acc[i][j]);
                        if (SPLITS == 3) {
                            wmma::mma_sync(acc[i][j], afh[i], bfl, acc[i][j]);
                            wmma::mma_sync(acc[i][j], afl[i], bfh, acc[i][j]);
                        }
                    }
                }
            }
        }
    };

    // 2-stage cp.async pipeline
    issue(0, 0);
    int cur = 0;
    for (int k0 = 0; k0 < K; k0 += 32) {
        bool more = (k0 + 32 < K);
        if (more) issue(k0 + 32, cur ^ 1);
        if (more) cp_wait<1>(); else cp_wait<0>();
        __syncthreads();
        compute(cur);
        __syncthreads();      // all warps done with 'cur' before it is refilled
        cur ^= 1;
    }

    // epilogue via smem staging (reuse pipeline smem)
    float* ep = (float*)smem + w * 2176;   // 32 x 68 per warp
#pragma unroll
    for (int i = 0; i < 2; i++)
#pragma unroll
        for (int j = 0; j < 4; j++)
            wmma::store_matrix_sync(ep + i * 16 * 68 + j * 16, acc[i][j], 68,
                                    wmma::mem_row_major);
    __syncwarp();
#pragma unroll 4
    for (int r = 0; r < 32; r++) {
        int gm = m0 + wm * 32 + r;
#pragma unroll
        for (int it = 0; it < 2; it++) {
            int gn = n0 + wn * 64 + it * 32 + lane;
            if (gn < N) {
                float v = ep[r * 68 + it * 32 + lane];
                if (EPI >= 1) v += bias[gn];
                if (EPI == 2) v = fmaxf(v, 0.f);
                size_t off = (size_t)gm * ldc + gn;
                if (C) C[off] = v;
                if (OH) {
                    bf16 h = __float2bfloat16_rn(v);
                    OH[off] = h;
                    if (OL) OL[off] = __float2bfloat16_rn(v - __bfloat162float(h));
                }
            }
        }
    }
}

// ---------------- approx top-64: 2-pass uint16 radix + margin gather --------
__global__ void __launch_bounds__(256) topk16_kernel()
{
    const int r = blockIdx.x, tid = threadIdx.x;
    const bf16* row = g_tau16 + (size_t)r * NMEM;
    const uint4* row4 = (const uint4*)row;          // 12500 uint4 per row
    __shared__ unsigned hist[256];
    __shared__ int sh_d, sh_need, cnt;

    // pass 1: histogram of key high byte
    hist[tid] = 0; __syncthreads();
    for (int i = tid; i < NMEM / 8; i += 256) {
        uint4 q = row4[i];
        unsigned short hb[8] = {
            (unsigned short)(q.x & 0xFFFFu), (unsigned short)(q.x >> 16),
            (unsigned short)(q.y & 0xFFFFu), (unsigned short)(q.y >> 16),
            (unsigned short)(q.z & 0xFFFFu), (unsigned short)(q.z >> 16),
            (unsigned short)(q.w & 0xFFFFu), (unsigned short)(q.w >> 16)};
#pragma unroll
        for (int t = 0; t < 8; t++)
            atomicAdd(&hist[f2key16(hb[t]) >> 8], 1u);
    }
    __syncthreads();
    if (tid == 0) {
        int cum = 0, d = 255;
        for (; d >= 0; --d) {
            if (cum + (int)hist[d] >= KTOP) break;
            cum += (int)hist[d];
        }
        if (d < 0) d = 0;
        sh_d = d; sh_need = KTOP - cum;
    }
    __syncthreads();
    const unsigned hi8 = (unsigned)sh_d;
    const int need = sh_need;
    __syncthreads();

    // pass 2: histogram of low byte among keys with matching high byte
    hist[tid] = 0; __syncthreads();
    for (int i = tid; i < NMEM / 8; i += 256) {
        uint4 q = row4[i];
        unsigned short hb[8] = {
            (unsigned short)(q.x & 0xFFFFu), (unsigned short)(q.x >> 16),
            (unsigned short)(q.y & 0xFFFFu), (unsigned short)(q.y >> 16),
            (unsigned short)(q.z & 0xFFFFu), (unsigned short)(q.z >> 16),
            (unsigned short)(q.w & 0xFFFFu), (unsigned short)(q.w >> 16)};
#pragma unroll
        for (int t = 0; t < 8; t++) {
            unsigned short k = f2key16(hb[t]);
            if ((k >> 8) == hi8) atomicAdd(&hist[k & 0xFFu], 1u);
        }
    }
    __syncthreads();
    if (tid == 0) {
        int cum = 0, d = 255;
        for (; d >= 0; --d) {
            if (cum + (int)hist[d] >= need) break;
            cum += (int)hist[d];
        }
        if (d < 0) d = 0;
        sh_d = d;
        cnt = 0;
    }
    __syncthreads();
    const unsigned short k64 = (unsigned short)((hi8 << 8) | (unsigned)sh_d);
    const float thr = key16_to_f(k64) - 2.0f;   // margin covers bf16+accum error
    __syncthreads();

    // gather candidates
    for (int i = tid; i < NMEM / 8; i += 256) {
        uint4 q = row4[i];
        unsigned short hb[8] = {
            (unsigned short)(q.x & 0xFFFFu), (unsigned short)(q.x >> 16),
            (unsigned short)(q.y & 0xFFFFu), (unsigned short)(q.y >> 16),
            (unsigned short)(q.z & 0xFFFFu), (unsigned short)(q.z >> 16),
            (unsigned short)(q.w & 0xFFFFu), (unsigned short)(q.w >> 16)};
#pragma unroll
        for (int t = 0; t < 8; t++) {
            __nv_bfloat16_raw br; br.x = hb[t];
            if (__bfloat162float((bf16)br) >= thr) {
                int p = atomicAdd(&cnt, 1);
                if (p < CAP) g_candidx[(size_t)r * CAP + p] = i * 8 + t;
            }
        }
    }
    __syncthreads();
    if (tid == 0) g_candcnt[r] = (cnt < CAP) ? cnt : CAP;
}

// ---------------- fp32 rescore (sequential-k fma, UNCHANGED) ----------------
__global__ void __launch_bounds__(256) rescore_kernel(
    const float* __restrict__ c, const float* __restrict__ mem_c)
{
    const int r = blockIdx.x, tid = threadIdx.x;
    __shared__ float sc[512];
    __shared__ float scores[CAP];
    __shared__ int   cidx[CAP];
    const int nc = g_candcnt[r];

    for (int k = tid; k < CDIM; k += 256) sc[k] = c[(size_t)r * CDIM + k];
    for (int i = tid; i < nc; i += 256) cidx[i] = g_candidx[(size_t)r * CAP + i];
    __syncthreads();

    for (int ci = tid; ci < nc; ci += 256) {
        const float* mr = mem_c + (size_t)cidx[ci] * CDIM;
        float s = 0.f;
#pragma unroll 8
        for (int k = 0; k < CDIM; k++) s = fmaf(sc[k], mr[k], s);
        scores[ci] = s;
    }
    __syncthreads();

    for (int ci = tid; ci < nc; ci += 256) {
        float v = scores[ci]; int id = cidx[ci];
        int rank = 0;
        for (int j = 0; j < nc; j++) {
            float vj = scores[j];
            rank += (vj > v) || (vj == v && cidx[j] < id);
        }
        if (rank < KTOP) {
            g_deltas[r * KTOP + rank] = v;
            g_topidx[r * KTOP + rank] = id;
        }
    }
}

// ---------------- mems = concat(delta, mem_c[idx]) + bf16 split -------------
__global__ void build_mems_kernel(const float* __restrict__ mem_c)
{
    const int row = blockIdx.x, tid = threadIdx.x;
    const int idx = g_topidx[row];
    const float d0 = g_deltas[row];
    float* out = g_mems + (size_t)row * DDIM;
    bf16*  oh  = g_ah  + (size_t)row * DDIM;
    bf16*  ol  = g_al  + (size_t)row * DDIM;
    const float* src = mem_c + (size_t)idx * CDIM;
    for (int cpos = tid; cpos < DDIM; cpos += blockDim.x) {
        float v = (cpos == 0) ? d0 : src[cpos - 1];
        out[cpos] = v;
        bf16 h = __float2bfloat16_rn(v);
        oh[cpos] = h;
        ol[cpos] = __float2bfloat16_rn(v - __bfloat162float(h));
    }
}

// ---------------- row LayerNorm (optional residual, optional split out) -----
__global__ void __launch_bounds__(256) ln_kernel(
    const float* __restrict__ x, const float* __restrict__ res,
    const float* __restrict__ g, const float* __restrict__ bb,
    float* __restrict__ out, bf16* __restrict__ oh, bf16* __restrict__ ol, int W)
{
    const int row = blockIdx.x, tid = threadIdx.x;
    const float* xr = x + (size_t)row * W;
    const float* rr = res ? res + (size_t)row * W : nullptr;
    __shared__ float s1[256], s2[256];
    float a = 0.f, a2 = 0.f;
    for (int cpos = tid; cpos < W; cpos += 256) {
        float v = xr[cpos] + (rr ? rr[cpos] : 0.f);
        a += v; a2 += v * v;
    }
    s1[tid] = a; s2[tid] = a2; __syncthreads();
    for (int o = 128; o > 0; o >>= 1) {
        if (tid < o) { s1[tid] += s1[tid + o]; s2[tid] += s2[tid + o]; }
        __syncthreads();
    }
    const float mu = s1[0] / W;
    const float var = s2[0] / W - mu * mu;
    const float rs = rsqrtf(var + 1e-5f);
    for (int cpos = tid; cpos < W; cpos += 256) {
        float v = xr[cpos] + (rr ? rr[cpos] : 0.f);
        float y = (v - mu) * rs * g[cpos] + bb[cpos];
        size_t off = (size_t)row * W + cpos;
        out[off] = y;
        if (oh) {
            bf16 h = __float2bfloat16_rn(y);
            oh[off] = h;
            ol[off] = __float2bfloat16_rn(y - __bfloat162float(h));
        }
    }
}

// ---------------- per-batch attention (64 tokens, ks=64, v=512) --------------
__global__ void __launch_bounds__(256) attn_kernel()
{
    extern __shared__ float smf[];
    float* sq = smf;
    float* sk = smf + 64 * 65;
    float* ss = smf + 2 * 64 * 65;
    const int b = blockIdx.x, tid = threadIdx.x;
    const float* qkv = g_qkvbuf + (size_t)b * 64 * TOTW;

    for (int e = tid; e < 4096; e += 256) {
        int i = e >> 6, d = e & 63;
        sq[i * 65 + d] = qkv[i * TOTW + d] * 0.125f;
        sk[i * 65 + d] = qkv[i * TOTW + KEYS + d];
    }
    __syncthreads();
    for (int e = tid; e < 4096; e += 256) {
        int i = e >> 6, j = e & 63;
        float acc = 0.f;
#pragma unroll 16
        for (int d = 0; d < 64; d++) acc += sq[i * 65 + d] * sk[j * 65 + d];
        ss[i * 65 + j] = acc;
    }
    __syncthreads();
    if (tid < 64) {
        float m = -1e30f;
        for (int j = 0; j < 64; j++) m = fmaxf(m, ss[tid * 65 + j]);
        float s = 0.f;
        for (int j = 0; j < 64; j++) { float e = expf(ss[tid * 65 + j] - m); ss[tid * 65 + j] = e; s += e; }
        float inv = 1.f / s;
        for (int j = 0; j < 64; j++) ss[tid * 65 + j] *= inv;
    }
    __syncthreads();
    float* vt = sq;
    for (int dc = 0; dc < DDIM; dc += 64) {
        for (int e = tid; e < 4096; e += 256) {
            int j = e >> 6, d = e & 63;
            vt[j * 65 + d] = qkv[j * TOTW + 2 * KEYS + dc + d];
        }
        __syncthreads();
        for (int e = tid; e < 4096; e += 256) {
            int i = e >> 6, d = e & 63;
            float acc = 0.f;
#pragma unroll 16
            for (int j = 0; j < 64; j++) acc += ss[i * 65 + j] * vt[j * 65 + d];
            g_att[(size_t)(b * 64 + i) * DDIM + dc + d] = acc;
        }
        __syncthreads();
    }
}

// ---------------- host orchestration -----------------------------------------
extern "C" void kernel_launch(void* const* d_in, const int* in_sizes, int n_in,
                              void* d_out, int out_size)
{
    const float* c     = (const float*)d_in[0];
    const float* mem_c = (const float*)d_in[1];
    const float* Wqkv  = (const float*)d_in[2];
    const float* bqkv  = (const float*)d_in[3];
    const float* gq    = (const float*)d_in[4];
    const float* bq    = (const float*)d_in[5];
    const float* gm    = (const float*)d_in[6];
    const float* bm    = (const float*)d_in[7];
    const float* W1    = (const float*)d_in[8];
    const float* b1    = (const float*)d_in[9];
    const float* W2    = (const float*)d_in[10];
    const float* b2    = (const float*)d_in[11];
    const float* Ws1   = (const float*)d_in[12];
    const float* bs1   = (const float*)d_in[13];
    const float* Ws2   = (const float*)d_in[14];
    const float* bs2   = (const float*)d_in[15];
    float* out = (float*)d_out;

    float *p_mems, *p_qkv, *p_att, *p_mem, *p_h, *p_t2;
    bf16 *p_tau16, *p_c16, *p_mc16, *p_ah, *p_al, *p_hh, *p_hl;
    bf16 *p_wqh, *p_wql, *p_w1h, *p_w1l, *p_w2h, *p_w2l, *p_s1h, *p_s1l, *p_s2h, *p_s2l;
    cudaGetSymbolAddress((void**)&p_tau16, g_tau16);
    cudaGetSymbolAddress((void**)&p_mems, g_mems);
    cudaGetSymbolAddress((void**)&p_qkv,  g_qkvbuf);
    cudaGetSymbolAddress((void**)&p_att,  g_att);
    cudaGetSymbolAddress((void**)&p_mem,  g_mem);
    cudaGetSymbolAddress((void**)&p_h,    g_h);
    cudaGetSymbolAddress((void**)&p_t2,   g_t2);
    cudaGetSymbolAddress((void**)&p_c16,  g_c16);
    cudaGetSymbolAddress((void**)&p_mc16, g_mc16);
    cudaGetSymbolAddress((void**)&p_ah,   g_ah);
    cudaGetSymbolAddress((void**)&p_al,   g_al);
    cudaGetSymbolAddress((void**)&p_hh,   g_hh);
    cudaGetSymbolAddress((void**)&p_hl,   g_hl);
    cudaGetSymbolAddress((void**)&p_wqh,  g_wqkv_h);
    cudaGetSymbolAddress((void**)&p_wql,  g_wqkv_l);
    cudaGetSymbolAddress((void**)&p_w1h,  g_w1_h);
    cudaGetSymbolAddress((void**)&p_w1l,  g_w1_l);
    cudaGetSymbolAddress((void**)&p_w2h,  g_w2_h);
    cudaGetSymbolAddress((void**)&p_w2l,  g_w2_l);
    cudaGetSymbolAddress((void**)&p_s1h,  g_ws1_h);
    cudaGetSymbolAddress((void**)&p_s1l,  g_ws1_l);
    cudaGetSymbolAddress((void**)&p_s2h,  g_ws2_h);
    cudaGetSymbolAddress((void**)&p_s2l,  g_ws2_l);

    const int WG_SMEM = 81920;
    cudaFuncSetAttribute(wgemm<1, 0, true>,  cudaFuncAttributeMaxDynamicSharedMemorySize, WG_SMEM);
    cudaFuncSetAttribute(wgemm<3, 1, false>, cudaFuncAttributeMaxDynamicSharedMemorySize, WG_SMEM);
    cudaFuncSetAttribute(wgemm<3, 2, false>, cudaFuncAttributeMaxDynamicSharedMemorySize, WG_SMEM);
    cudaFuncSetAttribute(attn_kernel, cudaFuncAttributeMaxDynamicSharedMemorySize,
                         3 * 64 * 65 * 4);
    const dim3 blk(256);

    // --- input/weight conversions ---
    split_pad_kernel<<<512, 256>>>(c,     p_c16,  nullptr, NB,   CDIM, DDIM);
    split_pad_kernel<<<2048, 256>>>(mem_c, p_mc16, nullptr, NMEM, CDIM, DDIM);
    split_pad_kernel<<<512, 256>>>(Wqkv, p_wqh, p_wql, DDIM, TOTW, TOTW);
    split_pad_kernel<<<512, 256>>>(W1,   p_w1h, p_w1l, DDIM, DDIM, DDIM);
    split_pad_kernel<<<512, 256>>>(W2,   p_w2h, p_w2l, DDIM, DDIM, DDIM);
    split_pad_kernel<<<512, 256>>>(Ws1,  p_s1h, p_s1l, DDIM, DDIM, DDIM);
    split_pad_kernel<<<512, 256>>>(Ws2,  p_s2h, p_s2l, DDIM, CDIM, DDIM);

    // --- 1) approx tau (bf16 out) = c16 @ mc16^T ---
    wgemm<1, 0, true><<<dim3((NMEM + 127) / 128, 2), blk, WG_SMEM>>>(
        p_c16, nullptr, p_mc16, nullptr, nullptr, nullptr, p_tau16, nullptr,
        NB, NMEM, DDIM, DDIM, DDIM, NMEM);

    // --- 2) 2-pass uint16 radix candidate select + exact fp32 rescore ---
    topk16_kernel<<<NB, blk>>>();
    rescore_kernel<<<NB, blk>>>(c, mem_c);

    // --- 3) mems + split ---
    build_mems_kernel<<<ROWS, 128>>>(mem_c);

    // --- 4) qkv = LN(mems @ Wqkv + bqkv) ---
    wgemm<3, 1, false><<<dim3(5, 128), blk, WG_SMEM>>>(
        p_ah, p_al, p_wqh, p_wql, bqkv, p_qkv, nullptr, nullptr,
        ROWS, TOTW, DDIM, DDIM, TOTW, TOTW);
    ln_kernel<<<ROWS, blk>>>(p_qkv, nullptr, gq, bq, p_qkv, nullptr, nullptr, TOTW);

    // --- 5) attention ---
    attn_kernel<<<NB, blk, 3 * 64 * 65 * 4>>>();

    // --- 6) mem = LN(mems + attended)  (+ split) ---
    ln_kernel<<<ROWS, blk>>>(p_mems, p_att, gm, bm, p_mem, p_ah, p_al, DDIM);

    // --- 7) two residual MLP blocks ---
    for (int rep = 0; rep < 2; rep++) {
        wgemm<3, 2, false><<<dim3(4, 128), blk, WG_SMEM>>>(
            p_ah, p_al, p_w1h, p_w1l, b1, nullptr, p_hh, p_hl,
            ROWS, DDIM, DDIM, DDIM, DDIM, DDIM);
        wgemm<3, 1, false><<<dim3(4, 128), blk, WG_SMEM>>>(
            p_hh, p_hl, p_w2h, p_w2l, b2, p_t2, nullptr, nullptr,
            ROWS, DDIM, DDIM, DDIM, DDIM, DDIM);
        ln_kernel<<<ROWS, blk>>>(p_t2, p_mem, gm, bm, p_mem, p_ah, p_al, DDIM);
    }

    // --- 8) c_prime = relu(mem @ Ws1 + bs1) @ Ws2 + bs2 ---
    wgemm<3, 2, false><<<dim3(4, 128), blk, WG_SMEM>>>(
        p_ah, p_al, p_s1h, p_s1l, bs1, nullptr, p_hh, p_hl,
        ROWS, DDIM, DDIM, DDIM, DDIM, DDIM);
    wgemm<3, 1, false><<<dim3(4, 128), blk, WG_SMEM>>>(
        p_hh, p_hl, p_s2h, p_s2l, bs2, out, nullptr, nullptr,
        ROWS, CDIM, DDIM, DDIM, DDIM, CDIM);
}